// round 4
// baseline (speedup 1.0000x reference)
#include <cuda_runtime.h>
#include <cooperative_groups.h>

namespace cg = cooperative_groups;

#define T_SEQ 4096
#define IN_DIM 512
#define H_DIM  256
#define G_DIM  1024   // 4*H
#define CLU    16     // CTAs per direction cluster

// ---------------- scratch (no allocation allowed -> device globals) ----------------
__device__ float g_x  [T_SEQ * IN_DIM];
__device__ float g_Gf [T_SEQ * G_DIM];
__device__ float g_Gb [T_SEQ * G_DIM];
__device__ float g_h0f[T_SEQ * H_DIM];
__device__ float g_h0b[T_SEQ * H_DIM];

// ---------------- PTX helpers ----------------
__device__ __forceinline__ unsigned long long ffma2(unsigned long long a,
                                                    unsigned long long b,
                                                    unsigned long long c)
{
    unsigned long long d;
    asm("fma.rn.f32x2 %0, %1, %2, %3;" : "=l"(d) : "l"(a), "l"(b), "l"(c));
    return d;
}
__device__ __forceinline__ unsigned long long packf2(float lo, float hi)
{
    unsigned long long d;
    asm("mov.b64 %0, {%1, %2};" : "=l"(d) : "f"(lo), "f"(hi));
    return d;
}
__device__ __forceinline__ float lof2(unsigned long long v)
{
    float f; asm("{ .reg .b32 hi; mov.b64 {%0, hi}, %1; }" : "=f"(f) : "l"(v)); return f;
}
__device__ __forceinline__ float hif2(unsigned long long v)
{
    float f; asm("{ .reg .b32 lo; mov.b64 {lo, %0}, %1; }" : "=f"(f) : "l"(v)); return f;
}
__device__ __forceinline__ unsigned smem_u32(const void* p)
{
    return (unsigned)__cvta_generic_to_shared(p);
}
__device__ __forceinline__ unsigned mapa_u32(unsigned addr, unsigned rank)
{
    unsigned r;
    asm("mapa.shared::cluster.u32 %0, %1, %2;" : "=r"(r) : "r"(addr), "r"(rank));
    return r;
}
__device__ __forceinline__ void mbar_init(unsigned bar, unsigned cnt)
{
    asm volatile("mbarrier.init.shared::cta.b64 [%0], %1;" :: "r"(bar), "r"(cnt) : "memory");
}
__device__ __forceinline__ void mbar_expect_tx(unsigned bar, unsigned bytes)
{
    asm volatile("mbarrier.arrive.expect_tx.shared::cta.b64 _, [%0], %1;"
                 :: "r"(bar), "r"(bytes) : "memory");
}
__device__ __forceinline__ void mbar_wait(unsigned bar, unsigned parity)
{
    asm volatile(
        "{\n\t"
        ".reg .pred P1;\n\t"
        "LW_%=:\n\t"
        "mbarrier.try_wait.parity.acquire.cta.shared::cta.b64 P1, [%0], %1, 0x989680;\n\t"
        "@P1 bra LD_%=;\n\t"
        "bra LW_%=;\n\t"
        "LD_%=:\n\t"
        "}"
        :: "r"(bar), "r"(parity) : "memory");
}
__device__ __forceinline__ void st_async_f32(unsigned dst, float val, unsigned rbar)
{
    asm volatile(
        "st.async.shared::cluster.mbarrier::complete_tx::bytes.b32 [%0], %1, [%2];"
        :: "r"(dst), "r"(__float_as_uint(val)), "r"(rbar) : "memory");
}

__device__ __forceinline__ float tanh_hw(float x)
{
    float y; asm("tanh.approx.f32 %0, %1;" : "=f"(y) : "f"(x)); return y;
}
__device__ __forceinline__ float sig_hw(float x)
{
    return __fmaf_rn(0.5f, tanh_hw(0.5f * x), 0.5f);
}

// ---------------- embedding gather ----------------
__global__ void embed_kernel(const int* __restrict__ tokens,
                             const float* __restrict__ emb,
                             float* __restrict__ x)
{
    int t = blockIdx.x;
    int tok = tokens[t];
    const float4* src = (const float4*)(emb + (size_t)tok * IN_DIM);
    float4* dst = (float4*)(x + (size_t)t * IN_DIM);
    dst[threadIdx.x] = src[threadIdx.x];
}

// ---------------- fused dual GEMM: C = A @ W^T + b1 + b2 (z selects direction) ----------------
// 128x128 tile, k-chunk 8, 8x8 per-thread accumulators.
__global__ __launch_bounds__(256)
void gemm_nt_bias2(const float* __restrict__ Af, const float* __restrict__ Ab,
                   const float* __restrict__ Wf, const float* __restrict__ Wb,
                   const float* __restrict__ b1f, const float* __restrict__ b2f,
                   const float* __restrict__ b1b, const float* __restrict__ b2b,
                   float* __restrict__ Cf, float* __restrict__ Cb,
                   int M, int N, int K, int revAb)
{
    const int z = blockIdx.z;
    const float* A  = z ? Ab  : Af;
    const float* W  = z ? Wb  : Wf;
    const float* b1 = z ? b1b : b1f;
    const float* b2 = z ? b2b : b2f;
    float* C        = z ? Cb  : Cf;
    const int revA  = z ? revAb : 0;

    __shared__ float As[8][128];
    __shared__ float Bs[8][128];

    const int bm = blockIdx.y * 128, bn = blockIdx.x * 128;
    const int tid = threadIdx.x;
    const int lrow = tid >> 1;            // 0..127
    const int lk   = (tid & 1) * 4;       // 0 or 4
    const int tx = tid & 15, ty = tid >> 4;

    float acc[8][8];
#pragma unroll
    for (int i = 0; i < 8; i++)
#pragma unroll
        for (int j = 0; j < 8; j++) acc[i][j] = 0.f;

    const int am = bm + lrow;
    const int as = revA ? (M - 1 - am) : am;
    const float* Arow = A + (size_t)as * K;
    const float* Wrow = W + (size_t)(bn + lrow) * K;

    for (int k0 = 0; k0 < K; k0 += 8) {
        float4 va = *(const float4*)(Arow + k0 + lk);
        float4 vb = *(const float4*)(Wrow + k0 + lk);
        __syncthreads();
        As[lk + 0][lrow] = va.x; As[lk + 1][lrow] = va.y;
        As[lk + 2][lrow] = va.z; As[lk + 3][lrow] = va.w;
        Bs[lk + 0][lrow] = vb.x; Bs[lk + 1][lrow] = vb.y;
        Bs[lk + 2][lrow] = vb.z; Bs[lk + 3][lrow] = vb.w;
        __syncthreads();
#pragma unroll
        for (int k = 0; k < 8; k++) {
            float a[8], b[8];
            *(float4*)&a[0] = *(const float4*)&As[k][ty * 8 + 0];
            *(float4*)&a[4] = *(const float4*)&As[k][ty * 8 + 4];
            *(float4*)&b[0] = *(const float4*)&Bs[k][tx * 8 + 0];
            *(float4*)&b[4] = *(const float4*)&Bs[k][tx * 8 + 4];
#pragma unroll
            for (int i = 0; i < 8; i++)
#pragma unroll
                for (int j = 0; j < 8; j++) acc[i][j] += a[i] * b[j];
        }
    }

#pragma unroll
    for (int i = 0; i < 8; i++) {
        int m = bm + ty * 8 + i;
        float* Crow = C + (size_t)m * N;
#pragma unroll
        for (int j = 0; j < 8; j++) {
            int n = bn + tx * 8 + j;
            Crow[n] = acc[i][j] + b1[n] + b2[n];
        }
    }
}

// ---------------- LSTM recurrence: 16-CTA cluster per direction ----------------
// CTA owns 16 hidden units; warp w owns units w*2 + {0,1}.
// Lane l: row r = l>>2 (0..7) = unit_in_warp(r>>2) * 4gates + gate(r&3); kq = l&3 (64 k each).
__global__ __launch_bounds__(256, 1) __cluster_dims__(CLU, 1, 1)
void lstm_layer_kernel(const float* __restrict__ Gf, const float* __restrict__ Gb,
                       const float* __restrict__ Whh_f, const float* __restrict__ Whh_b,
                       float* __restrict__ outf, float* __restrict__ outb,
                       int out_stride, int rev_out_b,
                       float* __restrict__ cellf, float* __restrict__ cellb,
                       float* __restrict__ hidf,  float* __restrict__ hidb)
{
    cg::cluster_group cluster = cg::this_cluster();
    const int crank = cluster.block_rank();
    const int dir   = blockIdx.x / CLU;

    const float* G    = dir ? Gb    : Gf;
    const float* Whh  = dir ? Whh_b : Whh_f;
    float* outp       = dir ? outb  : outf;
    float* cell_dst   = dir ? cellb : cellf;
    float* hid_dst    = dir ? hidb  : hidf;
    const int rev_out = dir ? rev_out_b : 0;

    const int tid = threadIdx.x;
    const int w   = tid >> 5;
    const int l   = tid & 31;
    const int r    = l >> 2;          // 0..7 gate-row in warp
    const int kq   = l & 3;           // k-quarter
    const int uiw  = r >> 2;          // 0..1
    const int gate = r & 3;
    const int gu_mine = crank * 16 + w * 2 + uiw;  // dot-product unit
    const int gu_ew   = crank * 16 + w * 2 + l;    // elementwise unit (lanes 0..1)

    __shared__ __align__(16) float hbuf[2][H_DIM];
    __shared__ __align__(8) unsigned long long barmem[2];

    const unsigned hbuf_a = smem_u32(&hbuf[0][0]);
    const unsigned bar_a  = smem_u32(&barmem[0]);

    // ---- Whh slice -> registers: 64 floats as 32 f32x2 ----
    unsigned long long w2[32];
    {
        const int grow = gate * H_DIM + gu_mine;
        const float4* wp = (const float4*)(Whh + (size_t)grow * H_DIM + kq * 64);
#pragma unroll
        for (int j = 0; j < 16; j++) {
            float4 v = wp[j];
            w2[2 * j + 0] = packf2(v.x, v.y);
            w2[2 * j + 1] = packf2(v.z, v.w);
        }
    }

    hbuf[0][tid] = 0.f;
    if (tid == 0) {
        mbar_init(bar_a + 0, 1);
        mbar_init(bar_a + 8, 1);
        mbar_expect_tx(bar_a + 0, 1024);   // serves step 2
        mbar_expect_tx(bar_a + 8, 1024);   // serves step 1
    }

    unsigned rhb[CLU], rbb[CLU];
#pragma unroll
    for (int rk = 0; rk < CLU; rk++) {
        rhb[rk] = mapa_u32(hbuf_a, rk);
        rbb[rk] = mapa_u32(bar_a, rk);
    }

    float cstate = 0.f;   // lanes 0..1 of each warp

    float gI = 0.f, gF = 0.f, gG = 0.f, gO = 0.f;
    if (l < 2) {
        const float* Gt = G + gu_ew;
        gI = __ldg(Gt);
        gF = __ldg(Gt + 256);
        gG = __ldg(Gt + 512);
        gO = __ldg(Gt + 768);
    }

    cluster.sync();

    for (int t = 0; t < T_SEQ; t++) {
        const int buf = t & 1, nb = buf ^ 1;

        if (t > 0) {
            mbar_wait(bar_a + 8 * buf, ((t - 1) >> 1) & 1);
            if (tid == 0) mbar_expect_tx(bar_a + 8 * buf, 1024);  // re-arm for t+2
        }

        // ---- recurrent dot: 64 MACs via 32 FFMA2, 4 accumulators ----
        unsigned long long a0 = 0ull, a1 = 0ull, a2 = 0ull, a3 = 0ull;
        const ulonglong2* hp = (const ulonglong2*)&hbuf[buf][kq * 64];
#pragma unroll
        for (int c = 0; c < 4; c++) {
            ulonglong2 hv[4];
#pragma unroll
            for (int q = 0; q < 4; q++) hv[q] = hp[c * 4 + q];
            a0 = ffma2(w2[c * 8 + 0], hv[0].x, a0);
            a1 = ffma2(w2[c * 8 + 1], hv[0].y, a1);
            a2 = ffma2(w2[c * 8 + 2], hv[1].x, a2);
            a3 = ffma2(w2[c * 8 + 3], hv[1].y, a3);
            a0 = ffma2(w2[c * 8 + 4], hv[2].x, a0);
            a1 = ffma2(w2[c * 8 + 5], hv[2].y, a1);
            a2 = ffma2(w2[c * 8 + 6], hv[3].x, a2);
            a3 = ffma2(w2[c * 8 + 7], hv[3].y, a3);
        }
        float v = (lof2(a0) + hif2(a0)) + (lof2(a1) + hif2(a1))
                + (lof2(a2) + hif2(a2)) + (lof2(a3) + hif2(a3));
        v += __shfl_xor_sync(0xffffffffu, v, 1);
        v += __shfl_xor_sync(0xffffffffu, v, 2);   // all 4 lanes of group r hold row sum

        // gather gates for lane l's unit (valid for lanes 0..1)
        float rI = __shfl_sync(0xffffffffu, v, (16 * l + 0) & 31);
        float rF = __shfl_sync(0xffffffffu, v, (16 * l + 4) & 31);
        float rG = __shfl_sync(0xffffffffu, v, (16 * l + 8) & 31);
        float rO = __shfl_sync(0xffffffffu, v, (16 * l + 12) & 31);

        if (l < 2) {
            float iv = rI + gI, fv = rF + gF, gv = rG + gG, ov = rO + gO;
            cstate = sig_hw(fv) * cstate + sig_hw(iv) * tanh_hw(gv);
            float h = sig_hw(ov) * tanh_hw(cstate);

            int orow = rev_out ? (T_SEQ - 1 - t) : t;
            outp[(size_t)orow * out_stride + gu_ew] = h;

            if (t < T_SEQ - 1) {
                const unsigned hoff = (unsigned)(nb * (H_DIM * 4) + gu_ew * 4);
                const unsigned boff = (unsigned)(8 * nb);
#pragma unroll
                for (int rk = 0; rk < CLU; rk++)
                    st_async_f32(rhb[rk] + hoff, h, rbb[rk] + boff);
            } else {
                cell_dst[gu_ew] = cstate;
                hid_dst[gu_ew]  = h;
            }
        }

        // prefetch G for step t+1
        if (l < 2 && t + 1 < T_SEQ) {
            const float* Gt = G + (size_t)(t + 1) * G_DIM + gu_ew;
            gI = __ldg(Gt);
            gF = __ldg(Gt + 256);
            gG = __ldg(Gt + 512);
            gO = __ldg(Gt + 768);
        }
    }
    cluster.sync();
}

// ---------------- launch ----------------
extern "C" void kernel_launch(void* const* d_in, const int* in_sizes, int n_in,
                              void* d_out, int out_size)
{
    const int*   tokens  = (const int*)  d_in[0];
    const float* emb     = (const float*)d_in[1];
    const float* f_Wih0  = (const float*)d_in[2];
    const float* f_Whh0  = (const float*)d_in[3];
    const float* f_bih0  = (const float*)d_in[4];
    const float* f_bhh0  = (const float*)d_in[5];
    const float* f_Wih1  = (const float*)d_in[6];
    const float* f_Whh1  = (const float*)d_in[7];
    const float* f_bih1  = (const float*)d_in[8];
    const float* f_bhh1  = (const float*)d_in[9];
    const float* b_Wih0  = (const float*)d_in[10];
    const float* b_Whh0  = (const float*)d_in[11];
    const float* b_bih0  = (const float*)d_in[12];
    const float* b_bhh0  = (const float*)d_in[13];
    const float* b_Wih1  = (const float*)d_in[14];
    const float* b_Whh1  = (const float*)d_in[15];
    const float* b_bih1  = (const float*)d_in[16];
    const float* b_bhh1  = (const float*)d_in[17];
    float* out = (float*)d_out;

    // allow 16-CTA clusters (idempotent; executes immediately, not a stream op)
    cudaFuncSetAttribute(lstm_layer_kernel,
                         cudaFuncAttributeNonPortableClusterSizeAllowed, 1);

    float *x, *Gf, *Gb, *h0f, *h0b;
    cudaGetSymbolAddress((void**)&x,   g_x);
    cudaGetSymbolAddress((void**)&Gf,  g_Gf);
    cudaGetSymbolAddress((void**)&Gb,  g_Gb);
    cudaGetSymbolAddress((void**)&h0f, g_h0f);
    cudaGetSymbolAddress((void**)&h0b, g_h0b);

    float* cell = out;            // (2,2,256)
    float* hid  = out + 1024;     // (2,2,256)
    float* outs = out + 2048;     // (4096,512)

    embed_kernel<<<T_SEQ, IN_DIM / 4>>>(tokens, emb, x);

    dim3 gemm_grid(G_DIM / 128, T_SEQ / 128, 2);

    gemm_nt_bias2<<<gemm_grid, 256>>>(x, x, f_Wih0, b_Wih0,
                                      f_bih0, f_bhh0, b_bih0, b_bhh0,
                                      Gf, Gb, T_SEQ, G_DIM, IN_DIM, 1);

    lstm_layer_kernel<<<2 * CLU, 256>>>(Gf, Gb, f_Whh0, b_Whh0,
                                        h0f, h0b, H_DIM, 0,
                                        cell + 0,   cell + 256,
                                        hid  + 0,   hid  + 256);

    gemm_nt_bias2<<<gemm_grid, 256>>>(h0f, h0b, f_Wih1, b_Wih1,
                                      f_bih1, f_bhh1, b_bih1, b_bhh1,
                                      Gf, Gb, T_SEQ, G_DIM, H_DIM, 0);

    lstm_layer_kernel<<<2 * CLU, 256>>>(Gf, Gb, f_Whh1, b_Whh1,
                                        outs, outs + 256, 2 * H_DIM, 1,
                                        cell + 512, cell + 768,
                                        hid  + 512, hid  + 768);
}

// round 5
// speedup vs baseline: 1.8550x; 1.8550x over previous
#include <cuda_runtime.h>
#include <cooperative_groups.h>

namespace cg = cooperative_groups;

#define T_SEQ 4096
#define IN_DIM 512
#define H_DIM  256
#define G_DIM  1024   // 4*H

// ---------------- scratch (no allocation allowed -> device globals) ----------------
__device__ float g_x  [T_SEQ * IN_DIM];
__device__ float g_Gf [T_SEQ * G_DIM];
__device__ float g_Gb [T_SEQ * G_DIM];
__device__ float g_h0f[T_SEQ * H_DIM];
__device__ float g_h0b[T_SEQ * H_DIM];

// ---------------- PTX helpers ----------------
__device__ __forceinline__ unsigned long long ffma2(unsigned long long a,
                                                    unsigned long long b,
                                                    unsigned long long c)
{
    unsigned long long d;
    asm("fma.rn.f32x2 %0, %1, %2, %3;" : "=l"(d) : "l"(a), "l"(b), "l"(c));
    return d;
}
__device__ __forceinline__ unsigned long long packf2(float lo, float hi)
{
    unsigned long long d;
    asm("mov.b64 %0, {%1, %2};" : "=l"(d) : "f"(lo), "f"(hi));
    return d;
}
__device__ __forceinline__ float lof2(unsigned long long v)
{
    float f; asm("{ .reg .b32 hi; mov.b64 {%0, hi}, %1; }" : "=f"(f) : "l"(v)); return f;
}
__device__ __forceinline__ float hif2(unsigned long long v)
{
    float f; asm("{ .reg .b32 lo; mov.b64 {lo, %0}, %1; }" : "=f"(f) : "l"(v)); return f;
}
__device__ __forceinline__ unsigned smem_u32(const void* p)
{
    return (unsigned)__cvta_generic_to_shared(p);
}
__device__ __forceinline__ unsigned mapa_u32(unsigned addr, unsigned rank)
{
    unsigned r;
    asm("mapa.shared::cluster.u32 %0, %1, %2;" : "=r"(r) : "r"(addr), "r"(rank));
    return r;
}
__device__ __forceinline__ void mbar_init(unsigned bar, unsigned cnt)
{
    asm volatile("mbarrier.init.shared::cta.b64 [%0], %1;" :: "r"(bar), "r"(cnt) : "memory");
}
__device__ __forceinline__ void mbar_expect_tx(unsigned bar, unsigned bytes)
{
    asm volatile("mbarrier.arrive.expect_tx.shared::cta.b64 _, [%0], %1;"
                 :: "r"(bar), "r"(bytes) : "memory");
}
__device__ __forceinline__ void mbar_wait(unsigned bar, unsigned parity)
{
    asm volatile(
        "{\n\t"
        ".reg .pred P1;\n\t"
        "LW_%=:\n\t"
        "mbarrier.try_wait.parity.acquire.cta.shared::cta.b64 P1, [%0], %1, 0x989680;\n\t"
        "@P1 bra LD_%=;\n\t"
        "bra LW_%=;\n\t"
        "LD_%=:\n\t"
        "}"
        :: "r"(bar), "r"(parity) : "memory");
}
__device__ __forceinline__ void st_async_f32(unsigned dst, float val, unsigned rbar)
{
    asm volatile(
        "st.async.shared::cluster.mbarrier::complete_tx::bytes.b32 [%0], %1, [%2];"
        :: "r"(dst), "r"(__float_as_uint(val)), "r"(rbar) : "memory");
}

__device__ __forceinline__ float tanh_hw(float x)
{
    float y; asm("tanh.approx.f32 %0, %1;" : "=f"(y) : "f"(x)); return y;
}
__device__ __forceinline__ float sig_hw(float x)
{
    return __fmaf_rn(0.5f, tanh_hw(0.5f * x), 0.5f);
}

// ---------------- embedding gather ----------------
__global__ void embed_kernel(const int* __restrict__ tokens,
                             const float* __restrict__ emb,
                             float* __restrict__ x)
{
    int t = blockIdx.x;
    int tok = tokens[t];
    const float4* src = (const float4*)(emb + (size_t)tok * IN_DIM);
    float4* dst = (float4*)(x + (size_t)t * IN_DIM);
    dst[threadIdx.x] = src[threadIdx.x];
}

// ---------------- fused dual GEMM: C = A @ W^T + b1 + b2 (z selects direction) ----------------
// 128x128 tile, k-chunk 8, 8x8 per-thread accumulators.  (validated in R4: 143us @ K=512)
__global__ __launch_bounds__(256)
void gemm_nt_bias2(const float* __restrict__ Af, const float* __restrict__ Ab,
                   const float* __restrict__ Wf, const float* __restrict__ Wb,
                   const float* __restrict__ b1f, const float* __restrict__ b2f,
                   const float* __restrict__ b1b, const float* __restrict__ b2b,
                   float* __restrict__ Cf, float* __restrict__ Cb,
                   int M, int N, int K, int revAb)
{
    const int z = blockIdx.z;
    const float* A  = z ? Ab  : Af;
    const float* W  = z ? Wb  : Wf;
    const float* b1 = z ? b1b : b1f;
    const float* b2 = z ? b2b : b2f;
    float* C        = z ? Cb  : Cf;
    const int revA  = z ? revAb : 0;

    __shared__ float As[8][128];
    __shared__ float Bs[8][128];

    const int bm = blockIdx.y * 128, bn = blockIdx.x * 128;
    const int tid = threadIdx.x;
    const int lrow = tid >> 1;            // 0..127
    const int lk   = (tid & 1) * 4;       // 0 or 4
    const int tx = tid & 15, ty = tid >> 4;

    float acc[8][8];
#pragma unroll
    for (int i = 0; i < 8; i++)
#pragma unroll
        for (int j = 0; j < 8; j++) acc[i][j] = 0.f;

    const int am = bm + lrow;
    const int as = revA ? (M - 1 - am) : am;
    const float* Arow = A + (size_t)as * K;
    const float* Wrow = W + (size_t)(bn + lrow) * K;

    for (int k0 = 0; k0 < K; k0 += 8) {
        float4 va = *(const float4*)(Arow + k0 + lk);
        float4 vb = *(const float4*)(Wrow + k0 + lk);
        __syncthreads();
        As[lk + 0][lrow] = va.x; As[lk + 1][lrow] = va.y;
        As[lk + 2][lrow] = va.z; As[lk + 3][lrow] = va.w;
        Bs[lk + 0][lrow] = vb.x; Bs[lk + 1][lrow] = vb.y;
        Bs[lk + 2][lrow] = vb.z; Bs[lk + 3][lrow] = vb.w;
        __syncthreads();
#pragma unroll
        for (int k = 0; k < 8; k++) {
            float a[8], b[8];
            *(float4*)&a[0] = *(const float4*)&As[k][ty * 8 + 0];
            *(float4*)&a[4] = *(const float4*)&As[k][ty * 8 + 4];
            *(float4*)&b[0] = *(const float4*)&Bs[k][tx * 8 + 0];
            *(float4*)&b[4] = *(const float4*)&Bs[k][tx * 8 + 4];
#pragma unroll
            for (int i = 0; i < 8; i++)
#pragma unroll
                for (int j = 0; j < 8; j++) acc[i][j] += a[i] * b[j];
        }
    }

#pragma unroll
    for (int i = 0; i < 8; i++) {
        int m = bm + ty * 8 + i;
        float* Crow = C + (size_t)m * N;
#pragma unroll
        for (int j = 0; j < 8; j++) {
            int n = bn + tx * 8 + j;
            Crow[n] = acc[i][j] + b1[n] + b2[n];
        }
    }
}

// ---------------- LSTM recurrence: 8-CTA cluster/direction, warp-autonomous units ----------------
// (R3 structure — best measured config — with MUFU.TANH elementwise)
// CTA owns 32 hidden units; warp w owns units [w*4, w*4+4).
// Lane l: r = l>>1 in 0..15 -> (unit_in_warp = r>>2, gate = r&3); kh = l&1 -> k-half.
__global__ __launch_bounds__(256, 1) __cluster_dims__(8, 1, 1)
void lstm_layer_kernel(const float* __restrict__ Gf, const float* __restrict__ Gb,
                       const float* __restrict__ Whh_f, const float* __restrict__ Whh_b,
                       float* __restrict__ outf, float* __restrict__ outb,
                       int out_stride, int rev_out_b,
                       float* __restrict__ cellf, float* __restrict__ cellb,
                       float* __restrict__ hidf,  float* __restrict__ hidb)
{
    cg::cluster_group cluster = cg::this_cluster();
    const int crank = cluster.block_rank();
    const int dir   = blockIdx.x >> 3;

    const float* G    = dir ? Gb    : Gf;
    const float* Whh  = dir ? Whh_b : Whh_f;
    float* outp       = dir ? outb  : outf;
    float* cell_dst   = dir ? cellb : cellf;
    float* hid_dst    = dir ? hidb  : hidf;
    const int rev_out = dir ? rev_out_b : 0;

    const int tid = threadIdx.x;
    const int w   = tid >> 5;
    const int l   = tid & 31;
    const int r   = l >> 1;
    const int kh  = l & 1;
    const int uiw  = r >> 2;
    const int gate = r & 3;
    const int gu_mine = crank * 32 + w * 4 + uiw;
    const int gu_ew   = crank * 32 + w * 4 + l;

    __shared__ __align__(16) float hbuf[2][H_DIM];
    __shared__ __align__(8) unsigned long long barmem[2];

    const unsigned hbuf_a = smem_u32(&hbuf[0][0]);
    const unsigned bar_a  = smem_u32(&barmem[0]);

    // ---- Whh slice -> registers: 128 floats as 64 f32x2 ----
    unsigned long long w2[64];
    {
        const int grow = gate * H_DIM + gu_mine;
        const float4* wp = (const float4*)(Whh + (size_t)grow * H_DIM + kh * 128);
#pragma unroll
        for (int j = 0; j < 32; j++) {
            float4 v = wp[j];
            w2[2 * j + 0] = packf2(v.x, v.y);
            w2[2 * j + 1] = packf2(v.z, v.w);
        }
    }

    hbuf[0][tid] = 0.f;
    if (tid == 0) {
        mbar_init(bar_a + 0, 1);
        mbar_init(bar_a + 8, 1);
        mbar_expect_tx(bar_a + 0, 1024);   // serves step 2
        mbar_expect_tx(bar_a + 8, 1024);   // serves step 1
    }

    unsigned rhb[8], rbb[8];
#pragma unroll
    for (int rk = 0; rk < 8; rk++) {
        rhb[rk] = mapa_u32(hbuf_a, rk);
        rbb[rk] = mapa_u32(bar_a, rk);
    }

    float cstate = 0.f;   // lanes 0..3 of each warp

    float gI = 0.f, gF = 0.f, gG = 0.f, gO = 0.f;
    if (l < 4) {
        const float* Gt = G + gu_ew;
        gI = __ldg(Gt);
        gF = __ldg(Gt + 256);
        gG = __ldg(Gt + 512);
        gO = __ldg(Gt + 768);
    }

    cluster.sync();

    for (int t = 0; t < T_SEQ; t++) {
        const int buf = t & 1, nb = buf ^ 1;

        if (t > 0) {
            mbar_wait(bar_a + 8 * buf, ((t - 1) >> 1) & 1);
            if (tid == 0) mbar_expect_tx(bar_a + 8 * buf, 1024);  // re-arm for t+2
        }

        // ---- recurrent dot: 128 MACs via 64 FFMA2, 4 accumulators, chunked h LDS ----
        unsigned long long a0 = 0ull, a1 = 0ull, a2 = 0ull, a3 = 0ull;
        const ulonglong2* hp = (const ulonglong2*)&hbuf[buf][kh * 128];
#pragma unroll
        for (int c = 0; c < 4; c++) {
            ulonglong2 hv[8];
#pragma unroll
            for (int q = 0; q < 8; q++) hv[q] = hp[c * 8 + q];
#pragma unroll
            for (int q = 0; q < 4; q++) {
                a0 = ffma2(w2[c * 16 + 4 * q + 0], hv[2 * q].x,     a0);
                a1 = ffma2(w2[c * 16 + 4 * q + 1], hv[2 * q].y,     a1);
                a2 = ffma2(w2[c * 16 + 4 * q + 2], hv[2 * q + 1].x, a2);
                a3 = ffma2(w2[c * 16 + 4 * q + 3], hv[2 * q + 1].y, a3);
            }
        }
        float v = (lof2(a0) + hif2(a0)) + (lof2(a1) + hif2(a1))
                + (lof2(a2) + hif2(a2)) + (lof2(a3) + hif2(a3));
        v += __shfl_xor_sync(0xffffffffu, v, 1);     // combine k-halves

        float rI = __shfl_sync(0xffffffffu, v, (8 * l + 0) & 31);
        float rF = __shfl_sync(0xffffffffu, v, (8 * l + 2) & 31);
        float rG = __shfl_sync(0xffffffffu, v, (8 * l + 4) & 31);
        float rO = __shfl_sync(0xffffffffu, v, (8 * l + 6) & 31);

        if (l < 4) {
            float iv = rI + gI, fv = rF + gF, gv = rG + gG, ov = rO + gO;
            cstate = sig_hw(fv) * cstate + sig_hw(iv) * tanh_hw(gv);
            float h = sig_hw(ov) * tanh_hw(cstate);

            int orow = rev_out ? (T_SEQ - 1 - t) : t;
            outp[(size_t)orow * out_stride + gu_ew] = h;

            if (t < T_SEQ - 1) {
                const unsigned hoff = (unsigned)(nb * (H_DIM * 4) + gu_ew * 4);
                const unsigned boff = (unsigned)(8 * nb);
#pragma unroll
                for (int rk = 0; rk < 8; rk++)
                    st_async_f32(rhb[rk] + hoff, h, rbb[rk] + boff);
            } else {
                cell_dst[gu_ew] = cstate;
                hid_dst[gu_ew]  = h;
            }
        }

        // prefetch G for step t+1
        if (l < 4 && t + 1 < T_SEQ) {
            const float* Gt = G + (size_t)(t + 1) * G_DIM + gu_ew;
            gI = __ldg(Gt);
            gF = __ldg(Gt + 256);
            gG = __ldg(Gt + 512);
            gO = __ldg(Gt + 768);
        }
    }
    cluster.sync();
}

// ---------------- launch ----------------
extern "C" void kernel_launch(void* const* d_in, const int* in_sizes, int n_in,
                              void* d_out, int out_size)
{
    const int*   tokens  = (const int*)  d_in[0];
    const float* emb     = (const float*)d_in[1];
    const float* f_Wih0  = (const float*)d_in[2];
    const float* f_Whh0  = (const float*)d_in[3];
    const float* f_bih0  = (const float*)d_in[4];
    const float* f_bhh0  = (const float*)d_in[5];
    const float* f_Wih1  = (const float*)d_in[6];
    const float* f_Whh1  = (const float*)d_in[7];
    const float* f_bih1  = (const float*)d_in[8];
    const float* f_bhh1  = (const float*)d_in[9];
    const float* b_Wih0  = (const float*)d_in[10];
    const float* b_Whh0  = (const float*)d_in[11];
    const float* b_bih0  = (const float*)d_in[12];
    const float* b_bhh0  = (const float*)d_in[13];
    const float* b_Wih1  = (const float*)d_in[14];
    const float* b_Whh1  = (const float*)d_in[15];
    const float* b_bih1  = (const float*)d_in[16];
    const float* b_bhh1  = (const float*)d_in[17];
    float* out = (float*)d_out;

    float *x, *Gf, *Gb, *h0f, *h0b;
    cudaGetSymbolAddress((void**)&x,   g_x);
    cudaGetSymbolAddress((void**)&Gf,  g_Gf);
    cudaGetSymbolAddress((void**)&Gb,  g_Gb);
    cudaGetSymbolAddress((void**)&h0f, g_h0f);
    cudaGetSymbolAddress((void**)&h0b, g_h0b);

    float* cell = out;            // (2,2,256)
    float* hid  = out + 1024;     // (2,2,256)
    float* outs = out + 2048;     // (4096,512)

    embed_kernel<<<T_SEQ, IN_DIM / 4>>>(tokens, emb, x);

    dim3 gemm_grid(G_DIM / 128, T_SEQ / 128, 2);

    gemm_nt_bias2<<<gemm_grid, 256>>>(x, x, f_Wih0, b_Wih0,
                                      f_bih0, f_bhh0, b_bih0, b_bhh0,
                                      Gf, Gb, T_SEQ, G_DIM, IN_DIM, 1);

    lstm_layer_kernel<<<16, 256>>>(Gf, Gb, f_Whh0, b_Whh0,
                                   h0f, h0b, H_DIM, 0,
                                   cell + 0,   cell + 256,
                                   hid  + 0,   hid  + 256);

    gemm_nt_bias2<<<gemm_grid, 256>>>(h0f, h0b, f_Wih1, b_Wih1,
                                      f_bih1, f_bhh1, b_bih1, b_bhh1,
                                      Gf, Gb, T_SEQ, G_DIM, H_DIM, 0);

    lstm_layer_kernel<<<16, 256>>>(Gf, Gb, f_Whh1, b_Whh1,
                                   outs, outs + 256, 2 * H_DIM, 1,
                                   cell + 512, cell + 768,
                                   hid  + 512, hid  + 768);
}